// round 1
// baseline (speedup 1.0000x reference)
#include <cuda_runtime.h>
#include <stdint.h>

// Problem constants (fixed by the dataset)
#define NLAT_IN  181
#define NLON_IN  360
#define NLAT_OUT 91
#define NLON_OUT 180
#define KS       9        // kernel_size = (3-1)*4+1
#define B_       4
#define CIN      32
#define COUT     32
#define BC       128      // B_*CIN
#define CK       288      // CIN*KS

#define WT       10       // longitudes per block (10 warps, 1 per w)
#define NWTILES  (NLON_OUT / WT)   // 18

#define MAX_NNZ  (2*1024*1024)

// ---------------- device scratch (no cudaMalloc allowed) ----------------
__device__ float g_xqt[NLAT_IN * NLON_IN * BC];   // 33.4 MB: xq transposed [pix][bc]
__device__ float g_wt[CK * COUT];                  // W transposed [ck][o]
__device__ int   g_hk[NLAT_OUT * KS + 1];          // (h,k) segment starts
__device__ int2  g_pack[MAX_NNZ];                  // per-nonzero: packed (row*360)<<9|lon, psi as bits
__device__ int   g_is64;                           // psi_idx dtype flag

// ---------------- dtype detection for psi_idx ----------------
// If psi_idx is int64, every odd 32-bit word (high half) is 0 because values < 2^16.
// If int32, words [nnz, 2*nnz) are the h array which is mostly nonzero.
__global__ void detect_kernel(const int* __restrict__ pidx, int nnz) {
    int bad = 0;
    for (int i = (nnz | 1); i < 2 * nnz; i += 64) bad |= pidx[i];
    g_is64 = (bad == 0) ? 1 : 0;
}

// ---------------- pack (row,lon,psi) per nonzero ----------------
__global__ void pack_kernel(const void* __restrict__ pidx,
                            const float* __restrict__ pvals, int nnz) {
    int e = blockIdx.x * blockDim.x + threadIdx.x;
    if (e >= nnz || e >= MAX_NNZ) return;
    int is64 = g_is64;
    int flat;
    if (is64) flat = (int)((const long long*)pidx)[2LL * nnz + e];
    else      flat = ((const int*)pidx)[2 * nnz + e];
    int row = flat / NLON_IN;
    int lon = flat - row * NLON_IN;
    int2 p;
    p.x = ((row * NLON_IN) << 9) | lon;
    p.y = __float_as_int(pvals[e]);
    g_pack[e] = p;
}

// ---------------- (h,k) segment boundaries ----------------
__global__ void hk_kernel(const void* __restrict__ pidx, int nnz) {
    int e = blockIdx.x * blockDim.x + threadIdx.x;
    if (e >= nnz) return;
    int is64 = g_is64;
    int k, h, kp = -1, hp = -1;
    if (is64) {
        k = (int)((const long long*)pidx)[e];
        h = (int)((const long long*)pidx)[(long long)nnz + e];
        if (e > 0) {
            kp = (int)((const long long*)pidx)[e - 1];
            hp = (int)((const long long*)pidx)[(long long)nnz + e - 1];
        }
    } else {
        k = ((const int*)pidx)[e];
        h = ((const int*)pidx)[nnz + e];
        if (e > 0) {
            kp = ((const int*)pidx)[e - 1];
            hp = ((const int*)pidx)[nnz + e - 1];
        }
    }
    int key  = h * KS + k;
    int prev = (e == 0) ? -1 : (hp * KS + kp);
    for (int t = prev + 1; t <= key; t++) g_hk[t] = e;
    if (e == nnz - 1)
        for (int t = key + 1; t <= NLAT_OUT * KS; t++) g_hk[t] = nnz;
}

// ---------------- transpose + quad-weight scale: x -> xq_t[pix][bc] ----------------
__global__ void xq_kernel(const float* __restrict__ x, const float* __restrict__ qw) {
    __shared__ float tile[32][33];
    int row = blockIdx.z;
    int lon0 = blockIdx.x * 32;
    int bc0 = blockIdx.y * 32;
    int tx = threadIdx.x, ty = threadIdx.y;   // 32 x 8
    float q = qw[row];
    for (int i = ty; i < 32; i += 8) {
        int lon = lon0 + tx;
        float v = 0.f;
        if (lon < NLON_IN)
            v = x[((size_t)(bc0 + i) * NLAT_IN + row) * NLON_IN + lon];
        tile[i][tx] = v * q;
    }
    __syncthreads();
    for (int i = ty; i < 32; i += 8) {
        int lon = lon0 + i;
        if (lon < NLON_IN)
            g_xqt[((size_t)(row * NLON_IN + lon)) * BC + bc0 + tx] = tile[tx][i];
    }
}

// ---------------- transpose W: [o][ck] -> [ck][o] ----------------
__global__ void wt_kernel(const float* __restrict__ w) {
    int id = blockIdx.x * blockDim.x + threadIdx.x;
    if (id >= COUT * CK) return;
    int o = id / CK;
    int ck = id - o * CK;
    g_wt[ck * COUT + o] = w[id];
}

// ---------------- fused conv kernel ----------------
// grid: (NWTILES=18, NLAT_OUT=91), block: 320 threads = 10 warps (1 warp per w)
__global__ void __launch_bounds__(WT * 32) conv_kernel(const float* __restrict__ bias,
                                                       float* __restrict__ out) {
    __shared__ float s_acc[WT * 4 * 289];   // [wslot*4 + b][ck], padded row 289

    int h = blockIdx.y;
    int wt = blockIdx.x;
    int lane = threadIdx.x & 31;
    int warp = threadIdx.x >> 5;            // wslot
    int w = wt * WT + warp;                 // global output longitude

    int boff = lane >> 3;                   // b (lane owns bc = lane*4 .. lane*4+3)
    int c0 = (lane & 7) * 4;
    int vbase = lane * 4;

    // ---- stage 1: y[b, c, k] for this (h, w), k-major register accumulation ----
    #pragma unroll 1
    for (int k = 0; k < KS; k++) {
        int e0 = g_hk[h * KS + k];
        int e1 = g_hk[h * KS + k + 1];
        float a0 = 0.f, a1 = 0.f, a2 = 0.f, a3 = 0.f;
        #pragma unroll 4
        for (int e = e0; e < e1; e++) {
            int2 pk = g_pack[e];
            int lon = pk.x & 511;
            int rb = pk.x >> 9;            // row*360
            float pv = __int_as_float(pk.y);
            int col = lon + 2 * w;
            col = (col >= NLON_IN) ? col - NLON_IN : col;
            const float4 v = *reinterpret_cast<const float4*>(
                &g_xqt[((size_t)(rb + col)) * BC + vbase]);
            a0 = fmaf(pv, v.x, a0);
            a1 = fmaf(pv, v.y, a1);
            a2 = fmaf(pv, v.z, a2);
            a3 = fmaf(pv, v.w, a3);
        }
        int sb = (warp * 4 + boff) * 289 + c0 * KS + k;
        s_acc[sb]          = a0;
        s_acc[sb + KS]     = a1;
        s_acc[sb + 2 * KS] = a2;
        s_acc[sb + 3 * KS] = a3;
    }
    __syncthreads();

    // ---- stage 2: out[b,o,h,w] = sum_ck W[o][ck] * y[b][ck] ; lane = o ----
    float r0 = 0.f, r1 = 0.f, r2 = 0.f, r3 = 0.f;
    int slot0 = warp * 4;                   // 4 (w',b) slots per warp, 40 total
    const float* s0 = &s_acc[(slot0 + 0) * 289];
    const float* s1 = &s_acc[(slot0 + 1) * 289];
    const float* s2 = &s_acc[(slot0 + 2) * 289];
    const float* s3 = &s_acc[(slot0 + 3) * 289];
    #pragma unroll 4
    for (int ck = 0; ck < CK; ck++) {
        float wv = g_wt[ck * COUT + lane];
        r0 = fmaf(wv, s0[ck], r0);
        r1 = fmaf(wv, s1[ck], r1);
        r2 = fmaf(wv, s2[ck], r2);
        r3 = fmaf(wv, s3[ck], r3);
    }
    float bo = bias[lane];
    float rr[4] = {r0, r1, r2, r3};
    #pragma unroll
    for (int p = 0; p < 4; p++) {
        int slot = slot0 + p;
        int wp = slot >> 2;                 // local wslot
        int bp = slot & 3;                  // b
        out[(((size_t)(bp * COUT + lane)) * NLAT_OUT + h) * NLON_OUT + (wt * WT + wp)]
            = rr[p] + bo;
    }
}

// ---------------- launch ----------------
extern "C" void kernel_launch(void* const* d_in, const int* in_sizes, int n_in,
                              void* d_out, int out_size) {
    const float* x      = (const float*)d_in[0];
    const float* qw     = (const float*)d_in[1];
    const float* pvals  = (const float*)d_in[2];
    const float* weight = (const float*)d_in[3];
    const float* bias   = (const float*)d_in[4];
    const void*  pidx   = d_in[5];
    float* out = (float*)d_out;

    int nnz = in_sizes[2];   // psi_vals element count

    detect_kernel<<<1, 1>>>((const int*)pidx, nnz);

    int tb = 256;
    pack_kernel<<<(nnz + tb - 1) / tb, tb>>>(pidx, pvals, nnz);
    hk_kernel<<<(nnz + tb - 1) / tb, tb>>>(pidx, nnz);

    dim3 xg((NLON_IN + 31) / 32, BC / 32, NLAT_IN);   // (12, 4, 181)
    xq_kernel<<<xg, dim3(32, 8)>>>(x, qw);

    wt_kernel<<<(COUT * CK + 255) / 256, 256>>>(weight);

    conv_kernel<<<dim3(NWTILES, NLAT_OUT), WT * 32>>>(bias, out);
}